// round 13
// baseline (speedup 1.0000x reference)
#include <cuda_runtime.h>
#include <math.h>
#include <stdint.h>

// Problem dims (fixed)
#define B_  64
#define T_  512
#define D_  256
#define H_  256
#define G4  1024          // 4*H
#define NBG 16            // batch groups (4 batches each) == clusters
#define CL  8             // CTAs per cluster (hidden slices of 32 units)
#define NB_SCAN (NBG*CL)  // 128 blocks
#define SENT 0x7FBFFFFFu  // NaN sentinel (unreachable from finite sigm*tanh)
#define NSLOT 4           // h ring depth (per-step slots, reused mod 4)

typedef unsigned long long u64;

// ---------------- device scratch ----------------
__device__ float g_Wc[G4 * D_];                 // combined weight W_ih @ W_att
__device__ float g_bc[G4];                      // combined bias
__device__ float g_vlin0[B_ * D_];              // vlin[:,0]
__device__ float g_a[B_ * T_];                  // attention scalars a[b,t]
__device__ float g_gates[(size_t)T_ * B_ * G4]; // input gates [t][b][grow]

// ---------------- helpers ----------------
__device__ __forceinline__ float sigm(float x) {
    return __fdividef(1.0f, 1.0f + __expf(-x));
}
__device__ __forceinline__ float tanh_fast(float x) {
    return fmaf(2.0f, __fdividef(1.0f, 1.0f + __expf(-2.0f * x)), -1.0f);
}
__device__ __forceinline__ u64 pack2(float x, float y) {
    u64 r;
    asm("mov.b64 %0, {%1, %2};" : "=l"(r) : "f"(x), "f"(y));
    return r;
}
__device__ __forceinline__ u64 fma2(u64 a, u64 b, u64 c) {
    u64 d;
    asm("fma.rn.f32x2 %0, %1, %2, %3;" : "=l"(d) : "l"(a), "l"(b), "l"(c));
    return d;
}
__device__ __forceinline__ float2 unpack2(u64 v) {
    float2 f;
    asm("mov.b64 {%0, %1}, %2;" : "=f"(f.x), "=f"(f.y) : "l"(v));
    return f;
}
__device__ __forceinline__ uint32_t smem_u32(const void* p) {
    uint32_t a;
    asm("{ .reg .u64 t; cvta.to.shared.u64 t, %1; cvt.u32.u64 %0, t; }" : "=r"(a) : "l"(p));
    return a;
}
__device__ __forceinline__ void st_cluster_u64(uint32_t addr, u64 v) {
    asm volatile("st.shared::cluster.b64 [%0], %1;" :: "r"(addr), "l"(v) : "memory");
}

// ---------------- kernel: Wc = W_ih @ W_att ----------------
__global__ void k_wc(const float* __restrict__ W_ih, const float* __restrict__ W_att) {
    int g = blockIdx.x;
    int k = threadIdx.x;
    __shared__ float wrow[D_];
    wrow[threadIdx.x] = W_ih[g * D_ + threadIdx.x];
    __syncthreads();
    float acc = 0.f;
#pragma unroll 8
    for (int d = 0; d < D_; d++) acc += wrow[d] * W_att[d * D_ + k];
    g_Wc[g * D_ + k] = acc;
}

// ---------------- kernel: bc = W_ih @ b_att + b_ih + b_hh ----------------
__global__ void k_bc(const float* __restrict__ W_ih, const float* __restrict__ b_att,
                     const float* __restrict__ b_ih, const float* __restrict__ b_hh) {
    __shared__ float ba[D_];
    if (threadIdx.x < D_) ba[threadIdx.x] = b_att[threadIdx.x];
    __syncthreads();
    int g = blockIdx.x * blockDim.x + threadIdx.x;
    if (g >= G4) return;
    float acc = b_ih[g] + b_hh[g];
#pragma unroll 8
    for (int d = 0; d < D_; d++) acc += W_ih[g * D_ + d] * ba[d];
    g_bc[g] = acc;
}

// ---------------- kernel: vlin0[b,:] = values[b,0,:] @ W_att^T + b_att ----------------
// warp-per-row: lanes stride k (coalesced W_att row reads), shuffle reduce.
__global__ void k_vlin0(const float* __restrict__ values, const float* __restrict__ W_att,
                        const float* __restrict__ b_att) {
    int b = blockIdx.x;
    int wrp = threadIdx.x >> 5;
    int lane = threadIdx.x & 31;
    __shared__ float v[D_];
    v[threadIdx.x] = values[(size_t)b * T_ * D_ + threadIdx.x];
    __syncthreads();
#pragma unroll
    for (int i = 0; i < 4; i++) {
        int d = wrp * 4 + i * 64 + 0;   // 8 warps x 4 rows x ... cover 256 rows
        d = wrp + i * 64;               // rows: wrp + 64*i .. plus stride below
        // each warp handles rows {wrp + 8*j : j} ; simpler: rows wrp*32/..
        (void)d;
    }
    // rows: warp w handles d = w*32 .. w*32+31
    for (int i = 0; i < 32; i++) {
        int d = wrp * 32 + i;
        const float* wr = W_att + (size_t)d * D_;
        float acc = 0.f;
#pragma unroll
        for (int k = lane; k < D_; k += 32) acc += v[k] * wr[k];
#pragma unroll
        for (int off = 16; off; off >>= 1) acc += __shfl_down_sync(0xffffffffu, acc, off);
        if (lane == 0) g_vlin0[b * D_ + d] = acc + b_att[d];
    }
}

// ---------------- kernel: a[b,t] = sigmoid(vlin0[b] . values[b,t]) ----------------
__global__ void k_a(const float* __restrict__ values) {
    int w = (blockIdx.x * blockDim.x + threadIdx.x) >> 5;
    int lane = threadIdx.x & 31;
    int b = w >> 9, t = w & (T_ - 1);
    const float* vp = values + ((size_t)b * T_ + t) * D_;
    const float* lp = g_vlin0 + b * D_;
    float acc = 0.f;
#pragma unroll
    for (int k = lane; k < D_; k += 32) acc += vp[k] * lp[k];
#pragma unroll
    for (int off = 16; off; off >>= 1) acc += __shfl_down_sync(0xffffffffu, acc, off);
    if (lane == 0) g_a[w] = 1.0f / (1.0f + expf(-acc));
}

// ---------------- big GEMM: gates[t][b][g] = values[b,t,:].Wc[g,:] + bc[g] ----------
// Tile: (64 batch x 2 t) rows x 128 n per block, 256 threads, 8x8 microtile (FFMA2).
#define PA 132   // smem row pitch (floats), float4-aligned
__global__ __launch_bounds__(256) void k_gemm(const float* __restrict__ values) {
    int t0 = blockIdx.x * 2;
    int n0 = blockIdx.y * 128;

    __shared__ float As[16 * PA];   // [k][r]  r = tt*64 + b
    __shared__ float Bs[16 * PA];   // [k][n]

    int tid = threadIdx.x;
    int tx = tid & 15;              // row quad group
    int ty = tid >> 4;              // n quad group

    const float* gp;
    float* scol;
    {
        int r = tid & 127;
        if (tid < 128) {
            int b = r & 63, tt = r >> 6;
            gp = values + ((size_t)b * T_ + t0 + tt) * D_;
            scol = As + r;
        } else {
            gp = g_Wc + (size_t)(n0 + r) * D_;
            scol = Bs + r;
        }
    }

    float4 pf0 = ((const float4*)gp)[0];
    float4 pf1 = ((const float4*)gp)[1];
    float4 pf2 = ((const float4*)gp)[2];
    float4 pf3 = ((const float4*)gp)[3];

    u64 acc[2][4][4];
#pragma unroll
    for (int a = 0; a < 2; a++)
#pragma unroll
        for (int i = 0; i < 4; i++)
#pragma unroll
            for (int j = 0; j < 4; j++) acc[a][i][j] = 0ull;

    for (int c = 0; c < 16; c++) {
        __syncthreads();
        scol[ 0 * PA] = pf0.x; scol[ 1 * PA] = pf0.y; scol[ 2 * PA] = pf0.z; scol[ 3 * PA] = pf0.w;
        scol[ 4 * PA] = pf1.x; scol[ 5 * PA] = pf1.y; scol[ 6 * PA] = pf1.z; scol[ 7 * PA] = pf1.w;
        scol[ 8 * PA] = pf2.x; scol[ 9 * PA] = pf2.y; scol[10 * PA] = pf2.z; scol[11 * PA] = pf2.w;
        scol[12 * PA] = pf3.x; scol[13 * PA] = pf3.y; scol[14 * PA] = pf3.z; scol[15 * PA] = pf3.w;
        __syncthreads();

        if (c < 15) {
            const float* np = gp + (c + 1) * 16;
            pf0 = ((const float4*)np)[0];
            pf1 = ((const float4*)np)[1];
            pf2 = ((const float4*)np)[2];
            pf3 = ((const float4*)np)[3];
        }

#pragma unroll
        for (int k = 0; k < 16; k++) {
            float4 a0 = *(const float4*)&As[k * PA + 4 * tx];
            float4 a1 = *(const float4*)&As[k * PA + 64 + 4 * tx];
            float4 bv0 = *(const float4*)&Bs[k * PA + 4 * ty];
            float4 bv1 = *(const float4*)&Bs[k * PA + 64 + 4 * ty];
            u64 b00 = *(u64*)&bv0.x;
            u64 b01 = *(u64*)&bv0.z;
            u64 b10 = *(u64*)&bv1.x;
            u64 b11 = *(u64*)&bv1.z;

            u64 p;
            p = pack2(a0.x, a0.x);
            acc[0][0][0] = fma2(p, b00, acc[0][0][0]); acc[0][0][1] = fma2(p, b01, acc[0][0][1]);
            acc[0][0][2] = fma2(p, b10, acc[0][0][2]); acc[0][0][3] = fma2(p, b11, acc[0][0][3]);
            p = pack2(a0.y, a0.y);
            acc[0][1][0] = fma2(p, b00, acc[0][1][0]); acc[0][1][1] = fma2(p, b01, acc[0][1][1]);
            acc[0][1][2] = fma2(p, b10, acc[0][1][2]); acc[0][1][3] = fma2(p, b11, acc[0][1][3]);
            p = pack2(a0.z, a0.z);
            acc[0][2][0] = fma2(p, b00, acc[0][2][0]); acc[0][2][1] = fma2(p, b01, acc[0][2][1]);
            acc[0][2][2] = fma2(p, b10, acc[0][2][2]); acc[0][2][3] = fma2(p, b11, acc[0][2][3]);
            p = pack2(a0.w, a0.w);
            acc[0][3][0] = fma2(p, b00, acc[0][3][0]); acc[0][3][1] = fma2(p, b01, acc[0][3][1]);
            acc[0][3][2] = fma2(p, b10, acc[0][3][2]); acc[0][3][3] = fma2(p, b11, acc[0][3][3]);
            p = pack2(a1.x, a1.x);
            acc[1][0][0] = fma2(p, b00, acc[1][0][0]); acc[1][0][1] = fma2(p, b01, acc[1][0][1]);
            acc[1][0][2] = fma2(p, b10, acc[1][0][2]); acc[1][0][3] = fma2(p, b11, acc[1][0][3]);
            p = pack2(a1.y, a1.y);
            acc[1][1][0] = fma2(p, b00, acc[1][1][0]); acc[1][1][1] = fma2(p, b01, acc[1][1][1]);
            acc[1][1][2] = fma2(p, b10, acc[1][1][2]); acc[1][1][3] = fma2(p, b11, acc[1][1][3]);
            p = pack2(a1.z, a1.z);
            acc[1][2][0] = fma2(p, b00, acc[1][2][0]); acc[1][2][1] = fma2(p, b01, acc[1][2][1]);
            acc[1][2][2] = fma2(p, b10, acc[1][2][2]); acc[1][2][3] = fma2(p, b11, acc[1][2][3]);
            p = pack2(a1.w, a1.w);
            acc[1][3][0] = fma2(p, b00, acc[1][3][0]); acc[1][3][1] = fma2(p, b01, acc[1][3][1]);
            acc[1][3][2] = fma2(p, b10, acc[1][3][2]); acc[1][3][3] = fma2(p, b11, acc[1][3][3]);
        }
    }

    float4 biasA = *(const float4*)&g_bc[n0 + 4 * ty];
    float4 biasB = *(const float4*)&g_bc[n0 + 64 + 4 * ty];
#pragma unroll
    for (int tt = 0; tt < 2; tt++) {
#pragma unroll
        for (int i = 0; i < 4; i++) {
            int b = 4 * tx + i;
            float* op = g_gates + ((size_t)(t0 + tt) * B_ + b) * G4 + n0;
            float2 p0 = unpack2(acc[tt][i][0]);
            float2 p1 = unpack2(acc[tt][i][1]);
            float2 p2 = unpack2(acc[tt][i][2]);
            float2 p3 = unpack2(acc[tt][i][3]);
            *(float4*)&op[4 * ty] =
                make_float4(p0.x + biasA.x, p0.y + biasA.y, p1.x + biasA.z, p1.y + biasA.w);
            *(float4*)&op[64 + 4 * ty] =
                make_float4(p2.x + biasB.x, p2.y + biasB.y, p3.x + biasB.z, p3.y + biasB.w);
        }
    }
}

// ---------------- persistent scan kernel (cluster DSMEM, sentinel data-as-tag) ----
// 16 clusters of 8 CTAs. Cluster g: batches 4g..4g+3; rank s: units 32s..32s+31.
// W_hh slice in REGISTERS. Producers push duplicated (h,h) u64 into a 4-deep SMEM
// ring slot of ALL peers (st.shared::cluster); consumers poll their LOCAL SMEM for
// the sentinel — no barriers, no flags, no L2 in the loop. alpha computed in-loop
// (register cumsum of Deltas). psum double-buffered by parity: one bar.sync/step.
__global__ __launch_bounds__(256, 1) __cluster_dims__(CL, 1, 1)
void k_scan(const float* __restrict__ Whh, const float* __restrict__ Deltas,
            float* __restrict__ out) {
    extern __shared__ float sm[];
    float* slots = sm;                         // NSLOT*8*256 = 8192 floats (32KB)
    u64* psumU = (u64*)(sm + NSLOT * 8 * 256); // 2 * 32*65 u64 (33.3KB)

    int tid = threadIdx.x;
    int bid = blockIdx.x;
    int g = bid >> 3;
    uint32_t s;
    asm("mov.u32 %0, %%cluster_ctarank;" : "=r"(s));

    int ks = tid >> 5;            // warp id == peer slice consumed
    int rq = tid & 31;            // row quad (rows 4rq..4rq+3)

    // ---- W slice into registers, pre-packed as row-pairs ----
    u64 wA[32], wB[32];
    {
        int r0 = 4 * rq;
        int q = r0 >> 5;
        int jb = r0 & 31;
        const float* wb = Whh + (size_t)(q * 256 + (int)s * 32 + jb) * 256 + 32 * ks;
#pragma unroll
        for (int kc = 0; kc < 32; kc++) {
            wA[kc] = pack2(wb[kc], wb[256 + kc]);
            wB[kc] = pack2(wb[512 + kc], wb[768 + kc]);
        }
    }

    // update identity (tid < 128)
    int ub = tid >> 5;            // 0..3 batch-local
    int jl = tid & 31;
    int bg = g * 4 + ub;          // global batch
    int jglob = (int)s * 32 + jl; // global hidden unit

    // DSMEM publish addresses: my (s,ub,jl) word inside each peer's slots array
    uint32_t slots_base = smem_u32(slots);
    uint32_t myoff = ((uint32_t)s * 256 + (uint32_t)ub * 64 + (uint32_t)jl * 2) * 4u;
    uint32_t ra[CL];
#pragma unroll
    for (int r = 0; r < CL; r++) {
        uint32_t t0a = slots_base + myoff;
        asm("mapa.shared::cluster.u32 %0, %1, %2;" : "=r"(ra[r]) : "r"(t0a), "r"(r));
    }

    // poison local slots (all NSLOT*8*256 floats)
    {
        uint4 sv = make_uint4(SENT, SENT, SENT, SENT);
        uint4* sp = (uint4*)slots;
        for (int i = tid; i < NSLOT * 8 * 256 / 4; i += 256) sp[i] = sv;
    }
    __syncthreads();
    asm volatile("barrier.cluster.arrive.aligned;" ::: "memory");
    asm volatile("barrier.cluster.wait.aligned;" ::: "memory");

    float c_reg = 0.f, c0_reg = 0.f, dacc = 0.f;

    // ---- prologue t = 0 (h=0, c=0; carry c stays zero — faithful quirk) ----
    if (tid < 128) {
        const float* g0 = g_gates + (size_t)bg * G4;
        float zi = g0[0 * H_ + jglob];
        float zg = g0[2 * H_ + jglob];
        float zo = g0[3 * H_ + jglob];
        c0_reg = sigm(zi) * tanh_fast(zg);
        float h1 = sigm(zo) * tanh_fast(c0_reg);
        dacc = Deltas[(size_t)bg * T_ * D_ + jglob];   // cumsum through t=0
        u64 hh = pack2(h1, h1);
#pragma unroll
        for (int r = 0; r < CL; r++) st_cluster_u64(ra[r], hh);   // slot 0
        out[(size_t)bg * (T_ * H_) + jglob] = h1;
    }

    // per-lane poll address stride: lane covers 8 floats of the 256-float fragment
    int lane = tid & 31;

    for (int t = 1; t < T_; t++) {
        // prefetch gates + Deltas + a (independent of poll, hides DRAM latency)
        float gin0 = 0.f, gin1 = 0.f, gin2 = 0.f, gin3 = 0.f, dlt = 0.f, av = 0.f;
        if (tid < 128) {
            const float* gt = g_gates + ((size_t)t * B_ + bg) * G4;
            gin0 = gt[0 * H_ + jglob];
            gin1 = gt[1 * H_ + jglob];
            gin2 = gt[2 * H_ + jglob];
            gin3 = gt[3 * H_ + jglob];
            dlt  = Deltas[((size_t)bg * T_ + t) * D_ + jglob];
            av   = g_a[bg * T_ + t];
        }

        int ps = (t - 1) & (NSLOT - 1);
        uint32_t frag_a = slots_base + (uint32_t)((ps * 8 + ks) * 256 + lane * 8) * 4u;

        // poll local fragment: data IS the tag
        {
            uint4 u1, u2;
            bool bad;
            do {
                asm volatile("ld.volatile.shared.v4.u32 {%0,%1,%2,%3}, [%4];"
                             : "=r"(u1.x), "=r"(u1.y), "=r"(u1.z), "=r"(u1.w)
                             : "r"(frag_a) : "memory");
                asm volatile("ld.volatile.shared.v4.u32 {%0,%1,%2,%3}, [%4];"
                             : "=r"(u2.x), "=r"(u2.y), "=r"(u2.z), "=r"(u2.w)
                             : "r"(frag_a + 16) : "memory");
                bad = (u1.x == SENT) | (u1.y == SENT) | (u1.z == SENT) | (u1.w == SENT) |
                      (u2.x == SENT) | (u2.y == SENT) | (u2.z == SENT) | (u2.w == SENT);
            } while (__any_sync(0xffffffffu, bad));
        }

        // dot: W in regs, h read directly from slot (dup-pairs), pure FFMA2
        {
            const float* hp = slots + (ps * 8 + ks) * 256;
            u64 a00 = 0, a01 = 0, a02 = 0, a03 = 0;
            u64 a10 = 0, a11 = 0, a12 = 0, a13 = 0;
#pragma unroll
            for (int m = 0; m < 16; m++) {
                float4 q0 = *(const float4*)(hp + 4 * m);
                float4 q1 = *(const float4*)(hp + 64 + 4 * m);
                float4 q2 = *(const float4*)(hp + 128 + 4 * m);
                float4 q3 = *(const float4*)(hp + 192 + 4 * m);
                u64 wa0 = wA[2 * m], wa1 = wA[2 * m + 1];
                u64 wb0 = wB[2 * m], wb1 = wB[2 * m + 1];
                u64 h00 = *(u64*)&q0.x, h01 = *(u64*)&q0.z;
                u64 h10 = *(u64*)&q1.x, h11 = *(u64*)&q1.z;
                u64 h20 = *(u64*)&q2.x, h21 = *(u64*)&q2.z;
                u64 h30 = *(u64*)&q3.x, h31 = *(u64*)&q3.z;
                a00 = fma2(wa0, h00, a00); a00 = fma2(wa1, h01, a00);
                a01 = fma2(wa0, h10, a01); a01 = fma2(wa1, h11, a01);
                a02 = fma2(wa0, h20, a02); a02 = fma2(wa1, h21, a02);
                a03 = fma2(wa0, h30, a03); a03 = fma2(wa1, h31, a03);
                a10 = fma2(wb0, h00, a10); a10 = fma2(wb1, h01, a10);
                a11 = fma2(wb0, h10, a11); a11 = fma2(wb1, h11, a11);
                a12 = fma2(wb0, h20, a12); a12 = fma2(wb1, h21, a12);
                a13 = fma2(wb0, h30, a13); a13 = fma2(wb1, h31, a13);
            }
            // re-poison the fragment words this lane owns (next write is step t+4)
            asm volatile("st.shared.v4.u32 [%0], {%1,%1,%1,%1};" :: "r"(frag_a), "r"(SENT) : "memory");
            asm volatile("st.shared.v4.u32 [%0], {%1,%1,%1,%1};" :: "r"(frag_a + 16), "r"(SENT) : "memory");

            u64* pb = psumU + (t & 1) * (32 * 65) + rq * 65 + ks * 4;
            pb[0] = a00; pb[1] = a01; pb[2] = a02; pb[3] = a03;
            pb[32 + 0] = a10; pb[32 + 1] = a11; pb[32 + 2] = a12; pb[32 + 3] = a13;
        }
        __syncthreads();   // psum[t&1] ready (single barrier per step)

        // cell update: 128 threads, one per (batch, unit)
        if (tid < 128) {
            const float* pf = (const float*)(psumU + (t & 1) * (32 * 65));
            int rqo = (jl >> 2);
            int off = ((jl >> 1) & 1) * 64 + ub * 2 + (jl & 1);
            float z[4] = {gin0, gin1, gin2, gin3};
#pragma unroll
            for (int q = 0; q < 4; q++) {
                const float* row = pf + (size_t)(q * 8 + rqo) * 130 + off;
                float sum = 0.f;
#pragma unroll
                for (int k8 = 0; k8 < 8; k8++) sum += row[k8 * 8];
                z[q] += sum;
            }
            dacc += dlt;
            float al = __fdividef(av, __logf(2.718281828459045f + dacc));
            float c = al * c0_reg + (1.f - al) * c_reg;
            c = sigm(z[1]) * c + sigm(z[0]) * tanh_fast(z[2]);
            c_reg = c;
            float h = sigm(z[3]) * tanh_fast(c);
            if (t < T_ - 1) {
                u64 hh = pack2(h, h);
                uint32_t so = (uint32_t)((t & (NSLOT - 1)) * 8 * 256) * 4u;
#pragma unroll
                for (int r = 0; r < CL; r++) st_cluster_u64(ra[r] + so, hh);
            }
            out[(size_t)bg * (T_ * H_) + (size_t)t * H_ + jglob] = h;
        }
        // no second barrier: psum double-buffered; slot reuse causally safe
    }

    // no CTA may exit while peers might still write into its SMEM
    asm volatile("barrier.cluster.arrive.aligned;" ::: "memory");
    asm volatile("barrier.cluster.wait.aligned;" ::: "memory");
}

// ---------------- launch ----------------
extern "C" void kernel_launch(void* const* d_in, const int* in_sizes, int n_in,
                              void* d_out, int out_size) {
    (void)in_sizes; (void)n_in; (void)out_size;
    const float* values = (const float*)d_in[0];
    const float* Deltas = (const float*)d_in[1];
    const float* W_att  = (const float*)d_in[2];
    const float* b_att  = (const float*)d_in[3];
    const float* W_ih   = (const float*)d_in[4];
    const float* W_hh   = (const float*)d_in[5];
    const float* b_ih   = (const float*)d_in[6];
    const float* b_hh   = (const float*)d_in[7];
    float* out = (float*)d_out;

    size_t smem = (size_t)(NSLOT * 8 * 256) * 4 + (size_t)2 * 32 * 65 * 8;  // 66048 B
    cudaFuncSetAttribute(k_scan, cudaFuncAttributeMaxDynamicSharedMemorySize, (int)smem);

    k_wc<<<G4, D_>>>(W_ih, W_att);
    k_bc<<<G4 / 256, 256>>>(W_ih, b_att, b_ih, b_hh);
    k_vlin0<<<B_, D_>>>(values, W_att, b_att);
    k_gemm<<<dim3(T_ / 2, G4 / 128), 256>>>(values);
    k_a<<<(B_ * T_ * 32) / 256, 256>>>(values);
    k_scan<<<NB_SCAN, 256, smem>>>(W_hh, Deltas, out);
}

// round 14
// speedup vs baseline: 1.4293x; 1.4293x over previous
#include <cuda_runtime.h>
#include <math.h>
#include <stdint.h>

// Problem dims (fixed)
#define B_  64
#define T_  512
#define D_  256
#define H_  256
#define G4  1024          // 4*H
#define NBG 16            // batch groups (4 batches each)
#define NSL 8             // hidden-slice blocks per group (32 units each)
#define NB_SCAN (NBG*NSL) // 128 blocks
#define SENT 0x7FBFFFFFu  // NaN sentinel (unreachable: gemm sums & sigm*tanh are finite)

typedef unsigned long long u64;
typedef unsigned int u32;

// ---------------- device scratch ----------------
__device__ float g_Wc[G4 * D_];                 // combined weight W_ih @ W_att
__device__ float g_bc[G4];                      // combined bias
__device__ float g_vlin0[B_ * D_];              // vlin[:,0]
__device__ float g_a[B_ * T_];                  // attention scalars a[b,t]
__device__ float g_gates[(size_t)T_ * B_ * G4]; // input gates [t][b][grow]  (sentinel-tagged)
__device__ float g_hT[(size_t)T_ * NBG * NSL * 128]; // per-step h fragments [t][g][s][jl][b]

#define N_HT_U4  ((size_t)T_ * NBG * NSL * 128 / 4)       // 2097152
#define N_GT_U4  ((size_t)T_ * B_ * G4 / 4)               // 8388608
#define N_POISON_U4 (N_HT_U4 + N_GT_U4)                   // 10485760

// ---------------- helpers ----------------
__device__ __forceinline__ float sigm(float x) {
    return __fdividef(1.0f, 1.0f + __expf(-x));
}
__device__ __forceinline__ float tanh_fast(float x) {
    return fmaf(2.0f, __fdividef(1.0f, 1.0f + __expf(-2.0f * x)), -1.0f);
}
__device__ __forceinline__ u64 pack2(float x, float y) {
    u64 r;
    asm("mov.b64 %0, {%1, %2};" : "=l"(r) : "f"(x), "f"(y));
    return r;
}
__device__ __forceinline__ u64 fma2(u64 a, u64 b, u64 c) {
    u64 d;
    asm("fma.rn.f32x2 %0, %1, %2, %3;" : "=l"(d) : "l"(a), "l"(b), "l"(c));
    return d;
}
__device__ __forceinline__ float2 unpack2(u64 v) {
    float2 f;
    asm("mov.b64 {%0, %1}, %2;" : "=f"(f.x), "=f"(f.y) : "l"(v));
    return f;
}
__device__ __forceinline__ uint4 ld_vol4(const float* p) {
    uint4 v;
    asm volatile("ld.volatile.global.v4.u32 {%0,%1,%2,%3}, [%4];"
                 : "=r"(v.x), "=r"(v.y), "=r"(v.z), "=r"(v.w) : "l"(p));
    return v;
}
__device__ __forceinline__ u32 ld_vol_u32(const u32* p) {
    u32 v;
    asm volatile("ld.volatile.global.u32 %0, [%1];" : "=r"(v) : "l"(p));
    return v;
}
__device__ __forceinline__ void st_vol(float* p, float v) {
    asm volatile("st.volatile.global.f32 [%0], %1;" :: "l"(p), "f"(v) : "memory");
}

// ---------------- kernel: poison h + gates buffers with sentinel ----------------
__global__ void k_poison() {
    size_t i = (size_t)blockIdx.x * blockDim.x + threadIdx.x;
    uint4 sv = make_uint4(SENT, SENT, SENT, SENT);
    if (i < N_HT_U4) ((uint4*)g_hT)[i] = sv;
    else if (i < N_POISON_U4) ((uint4*)g_gates)[i - N_HT_U4] = sv;
}

// ---------------- kernel: Wc = W_ih @ W_att ----------------
__global__ void k_wc(const float* __restrict__ W_ih, const float* __restrict__ W_att) {
    int g = blockIdx.x;
    int k = threadIdx.x;
    __shared__ float wrow[D_];
    wrow[threadIdx.x] = W_ih[g * D_ + threadIdx.x];
    __syncthreads();
    float acc = 0.f;
#pragma unroll 8
    for (int d = 0; d < D_; d++) acc += wrow[d] * W_att[d * D_ + k];
    g_Wc[g * D_ + k] = acc;
}

// ---------------- kernel: bc = W_ih @ b_att + b_ih + b_hh ----------------
__global__ void k_bc(const float* __restrict__ W_ih, const float* __restrict__ b_att,
                     const float* __restrict__ b_ih, const float* __restrict__ b_hh) {
    __shared__ float ba[D_];
    if (threadIdx.x < D_) ba[threadIdx.x] = b_att[threadIdx.x];
    __syncthreads();
    int g = blockIdx.x * blockDim.x + threadIdx.x;
    if (g >= G4) return;
    float acc = b_ih[g] + b_hh[g];
#pragma unroll 8
    for (int d = 0; d < D_; d++) acc += W_ih[g * D_ + d] * ba[d];
    g_bc[g] = acc;
}

// ---------------- kernel: vlin0[b,:] = values[b,0,:] @ W_att^T + b_att ----------------
// warp-per-row (coalesced W_att reads), shuffle reduce.
__global__ void k_vlin0(const float* __restrict__ values, const float* __restrict__ W_att,
                        const float* __restrict__ b_att) {
    int b = blockIdx.x;
    int wrp = threadIdx.x >> 5;
    int lane = threadIdx.x & 31;
    __shared__ float v[D_];
    v[threadIdx.x] = values[(size_t)b * T_ * D_ + threadIdx.x];
    __syncthreads();
    for (int i = 0; i < 32; i++) {
        int d = wrp * 32 + i;
        const float* wr = W_att + (size_t)d * D_;
        float acc = 0.f;
#pragma unroll
        for (int k = lane; k < D_; k += 32) acc += v[k] * wr[k];
#pragma unroll
        for (int off = 16; off; off >>= 1) acc += __shfl_down_sync(0xffffffffu, acc, off);
        if (lane == 0) g_vlin0[b * D_ + d] = acc + b_att[d];
    }
}

// ---------------- kernel: a[b,t] = sigmoid(vlin0[b] . values[b,t]) ----------------
__global__ void k_a(const float* __restrict__ values) {
    int w = (blockIdx.x * blockDim.x + threadIdx.x) >> 5;
    int lane = threadIdx.x & 31;
    int b = w >> 9, t = w & (T_ - 1);
    const float* vp = values + ((size_t)b * T_ + t) * D_;
    const float* lp = g_vlin0 + b * D_;
    float acc = 0.f;
#pragma unroll
    for (int k = lane; k < D_; k += 32) acc += vp[k] * lp[k];
#pragma unroll
    for (int off = 16; off; off >>= 1) acc += __shfl_down_sync(0xffffffffu, acc, off);
    if (lane == 0) g_a[w] = 1.0f / (1.0f + expf(-acc));
}

// ---------------- big GEMM: gates[t][b][g] = values[b,t,:].Wc[g,:] + bc[g] ----------
// Tile: (64 batch x 2 t) rows x 128 n per block, 256 threads, 8x8 microtile (FFMA2).
// Runs on a forked stream, OVERLAPPED with k_scan (scan polls gates via sentinel).
#define PA 132   // smem row pitch (floats), float4-aligned
__global__ __launch_bounds__(256) void k_gemm(const float* __restrict__ values) {
    int t0 = blockIdx.x * 2;
    int n0 = blockIdx.y * 128;

    __shared__ float As[16 * PA];   // [k][r]  r = tt*64 + b
    __shared__ float Bs[16 * PA];   // [k][n]

    int tid = threadIdx.x;
    int tx = tid & 15;              // row quad group
    int ty = tid >> 4;              // n quad group

    const float* gp;
    float* scol;
    {
        int r = tid & 127;
        if (tid < 128) {
            int b = r & 63, tt = r >> 6;
            gp = values + ((size_t)b * T_ + t0 + tt) * D_;
            scol = As + r;
        } else {
            gp = g_Wc + (size_t)(n0 + r) * D_;
            scol = Bs + r;
        }
    }

    float4 pf0 = ((const float4*)gp)[0];
    float4 pf1 = ((const float4*)gp)[1];
    float4 pf2 = ((const float4*)gp)[2];
    float4 pf3 = ((const float4*)gp)[3];

    u64 acc[2][4][4];
#pragma unroll
    for (int a = 0; a < 2; a++)
#pragma unroll
        for (int i = 0; i < 4; i++)
#pragma unroll
            for (int j = 0; j < 4; j++) acc[a][i][j] = 0ull;

    for (int c = 0; c < 16; c++) {
        __syncthreads();
        scol[ 0 * PA] = pf0.x; scol[ 1 * PA] = pf0.y; scol[ 2 * PA] = pf0.z; scol[ 3 * PA] = pf0.w;
        scol[ 4 * PA] = pf1.x; scol[ 5 * PA] = pf1.y; scol[ 6 * PA] = pf1.z; scol[ 7 * PA] = pf1.w;
        scol[ 8 * PA] = pf2.x; scol[ 9 * PA] = pf2.y; scol[10 * PA] = pf2.z; scol[11 * PA] = pf2.w;
        scol[12 * PA] = pf3.x; scol[13 * PA] = pf3.y; scol[14 * PA] = pf3.z; scol[15 * PA] = pf3.w;
        __syncthreads();

        if (c < 15) {
            const float* np = gp + (c + 1) * 16;
            pf0 = ((const float4*)np)[0];
            pf1 = ((const float4*)np)[1];
            pf2 = ((const float4*)np)[2];
            pf3 = ((const float4*)np)[3];
        }

#pragma unroll
        for (int k = 0; k < 16; k++) {
            float4 a0 = *(const float4*)&As[k * PA + 4 * tx];
            float4 a1 = *(const float4*)&As[k * PA + 64 + 4 * tx];
            float4 bv0 = *(const float4*)&Bs[k * PA + 4 * ty];
            float4 bv1 = *(const float4*)&Bs[k * PA + 64 + 4 * ty];
            u64 b00 = *(u64*)&bv0.x;
            u64 b01 = *(u64*)&bv0.z;
            u64 b10 = *(u64*)&bv1.x;
            u64 b11 = *(u64*)&bv1.z;

            u64 p;
            p = pack2(a0.x, a0.x);
            acc[0][0][0] = fma2(p, b00, acc[0][0][0]); acc[0][0][1] = fma2(p, b01, acc[0][0][1]);
            acc[0][0][2] = fma2(p, b10, acc[0][0][2]); acc[0][0][3] = fma2(p, b11, acc[0][0][3]);
            p = pack2(a0.y, a0.y);
            acc[0][1][0] = fma2(p, b00, acc[0][1][0]); acc[0][1][1] = fma2(p, b01, acc[0][1][1]);
            acc[0][1][2] = fma2(p, b10, acc[0][1][2]); acc[0][1][3] = fma2(p, b11, acc[0][1][3]);
            p = pack2(a0.z, a0.z);
            acc[0][2][0] = fma2(p, b00, acc[0][2][0]); acc[0][2][1] = fma2(p, b01, acc[0][2][1]);
            acc[0][2][2] = fma2(p, b10, acc[0][2][2]); acc[0][2][3] = fma2(p, b11, acc[0][2][3]);
            p = pack2(a0.w, a0.w);
            acc[0][3][0] = fma2(p, b00, acc[0][3][0]); acc[0][3][1] = fma2(p, b01, acc[0][3][1]);
            acc[0][3][2] = fma2(p, b10, acc[0][3][2]); acc[0][3][3] = fma2(p, b11, acc[0][3][3]);
            p = pack2(a1.x, a1.x);
            acc[1][0][0] = fma2(p, b00, acc[1][0][0]); acc[1][0][1] = fma2(p, b01, acc[1][0][1]);
            acc[1][0][2] = fma2(p, b10, acc[1][0][2]); acc[1][0][3] = fma2(p, b11, acc[1][0][3]);
            p = pack2(a1.y, a1.y);
            acc[1][1][0] = fma2(p, b00, acc[1][1][0]); acc[1][1][1] = fma2(p, b01, acc[1][1][1]);
            acc[1][1][2] = fma2(p, b10, acc[1][1][2]); acc[1][1][3] = fma2(p, b11, acc[1][1][3]);
            p = pack2(a1.z, a1.z);
            acc[1][2][0] = fma2(p, b00, acc[1][2][0]); acc[1][2][1] = fma2(p, b01, acc[1][2][1]);
            acc[1][2][2] = fma2(p, b10, acc[1][2][2]); acc[1][2][3] = fma2(p, b11, acc[1][2][3]);
            p = pack2(a1.w, a1.w);
            acc[1][3][0] = fma2(p, b00, acc[1][3][0]); acc[1][3][1] = fma2(p, b01, acc[1][3][1]);
            acc[1][3][2] = fma2(p, b10, acc[1][3][2]); acc[1][3][3] = fma2(p, b11, acc[1][3][3]);
        }
    }

    float4 biasA = *(const float4*)&g_bc[n0 + 4 * ty];
    float4 biasB = *(const float4*)&g_bc[n0 + 64 + 4 * ty];
#pragma unroll
    for (int tt = 0; tt < 2; tt++) {
#pragma unroll
        for (int i = 0; i < 4; i++) {
            int b = 4 * tx + i;
            float* op = g_gates + ((size_t)(t0 + tt) * B_ + b) * G4 + n0;
            float2 p0 = unpack2(acc[tt][i][0]);
            float2 p1 = unpack2(acc[tt][i][1]);
            float2 p2 = unpack2(acc[tt][i][2]);
            float2 p3 = unpack2(acc[tt][i][3]);
            *(float4*)&op[4 * ty] =
                make_float4(p0.x + biasA.x, p0.y + biasA.y, p1.x + biasA.z, p1.y + biasA.w);
            *(float4*)&op[64 + 4 * ty] =
                make_float4(p2.x + biasB.x, p2.y + biasB.y, p3.x + biasB.z, p3.y + biasB.w);
        }
    }
}

// ---------------- persistent scan kernel (L2 data-as-tag, gemm-overlapped) --------
// 128 blocks = 16 groups x 8 slices. Block (g,s): batches 4g..4g+3, units 32s..32s+31.
// W rows 4rq,4rq+1 in REGISTERS; rows 4rq+2,4rq+3 in thread-private SMEM (register
// relief so a gemm block co-resides on the same SM). h exchange: per-step sentinel
// buffers in L2 (proven R12). gates ALSO sentinel-polled -> gemm runs concurrently.
// alpha computed in-loop (register cumsum of Deltas). One __syncthreads per step.
__global__ __launch_bounds__(256, 1) void k_scan(const float* __restrict__ Whh,
                                                 const float* __restrict__ Deltas,
                                                 float* __restrict__ out) {
    extern __shared__ float sm[];
    float* h_s2 = sm;                          // 8*256 floats (8KB) [ks][dup-pair frags]
    float* wBs  = sm + 8 * 256;                // 16384 floats (64KB) [m][ks][rq] float4
    u64* psumU  = (u64*)(sm + 8 * 256 + 16384);// 2 * 32*65 u64 (33.3KB), parity-buffered

    int tid = threadIdx.x;
    int bid = blockIdx.x;
    int g = bid >> 3, s = bid & 7;

    int ks = tid >> 5;            // warp id == peer slice consumed
    int rq = tid & 31;            // row quad (rows 4rq..4rq+3)

    // ---- W slice: rows 4rq,4rq+1 -> regs; rows 4rq+2,4rq+3 -> private smem ----
    u64 wA[32];
    {
        int r0 = 4 * rq;
        int q = r0 >> 5;
        int jb = r0 & 31;
        const float* wb = Whh + (size_t)(q * 256 + s * 32 + jb) * 256 + 32 * ks;
#pragma unroll
        for (int kc = 0; kc < 32; kc++) wA[kc] = pack2(wb[kc], wb[256 + kc]);
        float4* w4 = (float4*)wBs;
#pragma unroll
        for (int m = 0; m < 16; m++) {
            u64 b0 = pack2(wb[512 + 2 * m],     wb[768 + 2 * m]);
            u64 b1 = pack2(wb[512 + 2 * m + 1], wb[768 + 2 * m + 1]);
            float4 q4;
            *(u64*)&q4.x = b0;
            *(u64*)&q4.z = b1;
            w4[(m * 8 + ks) * 32 + rq] = q4;   // written & read by this thread only
        }
    }

    // update identity (tid < 128)
    int ub = tid >> 5;            // 0..3 batch-local
    int jl = tid & 31;
    int bg = g * 4 + ub;          // global batch
    int jglob = s * 32 + jl;      // global hidden unit

    float c_reg = 0.f, c0_reg = 0.f, dacc = 0.f;

    // ---- prologue t = 0 (h=0, c=0; carry c stays zero — faithful quirk) ----
    if (tid < 128) {
        const u32* g0 = (const u32*)(g_gates + (size_t)bg * G4);
        u32 uzi, uzg, uzo;
        do {
            uzi = ld_vol_u32(g0 + jglob);
            uzg = ld_vol_u32(g0 + 512 + jglob);
            uzo = ld_vol_u32(g0 + 768 + jglob);
        } while (uzi == SENT || uzg == SENT || uzo == SENT);
        float zi = __uint_as_float(uzi);
        float zg = __uint_as_float(uzg);
        float zo = __uint_as_float(uzo);
        c0_reg = sigm(zi) * tanh_fast(zg);
        float h1 = sigm(zo) * tanh_fast(c0_reg);
        dacc = Deltas[(size_t)bg * T_ * D_ + jglob];   // cumsum through t=0
        st_vol(g_hT + (((size_t)0 * NBG + g) * NSL + s) * 128 + jl * 4 + ub, h1);
        out[(size_t)bg * (T_ * H_) + jglob] = h1;
    }

    for (int t = 1; t < T_; t++) {
        // early volatile prefetch of gates/Deltas/a (sentinel re-check after barrier)
        u32 ug0 = SENT, ug1 = SENT, ug2 = SENT, ug3 = SENT;
        float dlt = 0.f, av = 0.f;
        const u32* gt = (const u32*)(g_gates + ((size_t)t * B_ + bg) * G4);
        if (tid < 128) {
            ug0 = ld_vol_u32(gt + jglob);
            ug1 = ld_vol_u32(gt + 256 + jglob);
            ug2 = ld_vol_u32(gt + 512 + jglob);
            ug3 = ld_vol_u32(gt + 768 + jglob);
            dlt = Deltas[((size_t)bg * T_ + t) * D_ + jglob];
            av  = g_a[bg * T_ + t];
        }

        // poll peer h fragment: data IS the tag (proven R12 protocol)
        {
            const float* fp = g_hT + (((size_t)(t - 1) * NBG + g) * NSL + ks) * 128 + rq * 4;
            uint4 u;
            do {
                u = ld_vol4(fp);
            } while (u.x == SENT || u.y == SENT || u.z == SENT || u.w == SENT);
            float2* d = (float2*)(h_s2 + ks * 256);
            float hx = __uint_as_float(u.x);
            float hy = __uint_as_float(u.y);
            float hz = __uint_as_float(u.z);
            float hw = __uint_as_float(u.w);
            d[0 * 32 + rq] = make_float2(hx, hx);
            d[1 * 32 + rq] = make_float2(hy, hy);
            d[2 * 32 + rq] = make_float2(hz, hz);
            d[3 * 32 + rq] = make_float2(hw, hw);
        }
        __syncwarp();

        // dot: wA in regs, wB via private LDS.128, h via broadcast LDS.128, FFMA2
        {
            const float* hp = h_s2 + ks * 256;
            const float4* wbp = (const float4*)wBs + ks * 32 + rq;
            u64 a00 = 0, a01 = 0, a02 = 0, a03 = 0;
            u64 a10 = 0, a11 = 0, a12 = 0, a13 = 0;
#pragma unroll
            for (int m = 0; m < 16; m++) {
                float4 q0 = *(const float4*)(hp + 4 * m);
                float4 q1 = *(const float4*)(hp + 64 + 4 * m);
                float4 q2 = *(const float4*)(hp + 128 + 4 * m);
                float4 q3 = *(const float4*)(hp + 192 + 4 * m);
                float4 wq = wbp[m * 256];
                u64 wa0 = wA[2 * m], wa1 = wA[2 * m + 1];
                u64 wb0 = *(u64*)&wq.x, wb1 = *(u64*)&wq.z;
                u64 h00 = *(u64*)&q0.x, h01 = *(u64*)&q0.z;
                u64 h10 = *(u64*)&q1.x, h11 = *(u64*)&q1.z;
                u64 h20 = *(u64*)&q2.x, h21 = *(u64*)&q2.z;
                u64 h30 = *(u64*)&q3.x, h31 = *(u64*)&q3.z;
                a00 = fma2(wa0, h00, a00); a00 = fma2(wa1, h01, a00);
                a01 = fma2(wa0, h10, a01); a01 = fma2(wa1, h11, a01);
                a02 = fma2(wa0, h20, a02); a02 = fma2(wa1, h21, a02);
                a03 = fma2(wa0, h30, a03); a03 = fma2(wa1, h31, a03);
                a10 = fma2(wb0, h00, a10); a10 = fma2(wb1, h01, a10);
                a11 = fma2(wb0, h10, a11); a11 = fma2(wb1, h11, a11);
                a12 = fma2(wb0, h20, a12); a12 = fma2(wb1, h21, a12);
                a13 = fma2(wb0, h30, a13); a13 = fma2(wb1, h31, a13);
            }
            u64* pb = psumU + (t & 1) * (32 * 65) + rq * 65 + ks * 4;
            pb[0] = a00; pb[1] = a01; pb[2] = a02; pb[3] = a03;
            pb[32 + 0] = a10; pb[32 + 1] = a11; pb[32 + 2] = a12; pb[32 + 3] = a13;
        }
        __syncthreads();   // psum[t&1] ready (single barrier per step; parity-buffered)

        // cell update: 128 threads, one per (batch, unit)
        if (tid < 128) {
            // finish gates poll (normally already satisfied by the prefetch)
            while (ug0 == SENT || ug1 == SENT || ug2 == SENT || ug3 == SENT) {
                ug0 = ld_vol_u32(gt + jglob);
                ug1 = ld_vol_u32(gt + 256 + jglob);
                ug2 = ld_vol_u32(gt + 512 + jglob);
                ug3 = ld_vol_u32(gt + 768 + jglob);
            }
            const float* pf = (const float*)(psumU + (t & 1) * (32 * 65));
            int rqo = (jl >> 2);
            int off = ((jl >> 1) & 1) * 64 + ub * 2 + (jl & 1);
            float z[4] = {__uint_as_float(ug0), __uint_as_float(ug1),
                          __uint_as_float(ug2), __uint_as_float(ug3)};
#pragma unroll
            for (int q = 0; q < 4; q++) {
                const float* row = pf + (size_t)(q * 8 + rqo) * 130 + off;
                float sum = 0.f;
#pragma unroll
                for (int k8 = 0; k8 < 8; k8++) sum += row[k8 * 8];
                z[q] += sum;
            }
            dacc += dlt;
            float al = __fdividef(av, __logf(2.718281828459045f + dacc));
            float c = al * c0_reg + (1.f - al) * c_reg;
            c = sigm(z[1]) * c + sigm(z[0]) * tanh_fast(z[2]);
            c_reg = c;
            float h = sigm(z[3]) * tanh_fast(c);
            if (t < T_ - 1)
                st_vol(g_hT + (((size_t)t * NBG + g) * NSL + s) * 128 + jl * 4 + ub, h);
            out[(size_t)bg * (T_ * H_) + (size_t)t * H_ + jglob] = h;
        }
        // no second barrier: psum parity-buffered; h_s2 fragments warp-private
    }
}

// ---------------- launch ----------------
extern "C" void kernel_launch(void* const* d_in, const int* in_sizes, int n_in,
                              void* d_out, int out_size) {
    (void)in_sizes; (void)n_in; (void)out_size;
    const float* values = (const float*)d_in[0];
    const float* Deltas = (const float*)d_in[1];
    const float* W_att  = (const float*)d_in[2];
    const float* b_att  = (const float*)d_in[3];
    const float* W_ih   = (const float*)d_in[4];
    const float* W_hh   = (const float*)d_in[5];
    const float* b_ih   = (const float*)d_in[6];
    const float* b_hh   = (const float*)d_in[7];
    float* out = (float*)d_out;

    const size_t smem = (size_t)(8 * 256 + 16384) * 4 + (size_t)2 * 32 * 65 * 8; // 107008 B

    static cudaStream_t s2 = nullptr;
    static cudaEvent_t ev1 = nullptr, ev2 = nullptr;
    if (!s2) {   // first call = eager correctness run (not under capture)
        cudaStreamCreateWithFlags(&s2, cudaStreamNonBlocking);
        cudaEventCreateWithFlags(&ev1, cudaEventDisableTiming);
        cudaEventCreateWithFlags(&ev2, cudaEventDisableTiming);
        cudaFuncSetAttribute(k_scan, cudaFuncAttributeMaxDynamicSharedMemorySize, (int)smem);
    }

    // sequential pre-pass on the capture stream
    k_poison<<<(int)(N_POISON_U4 / 256), 256>>>();
    k_wc<<<G4, D_>>>(W_ih, W_att);
    k_bc<<<G4 / 256, 256>>>(W_ih, b_att, b_ih, b_hh);
    k_vlin0<<<B_, D_>>>(values, W_att, b_att);
    k_a<<<(B_ * T_ * 32) / 256, 256>>>(values);

    // fork: gemm on side stream, scan on capture stream — overlapped via gates sentinel
    cudaEventRecord(ev1, 0);
    cudaStreamWaitEvent(s2, ev1, 0);
    k_gemm<<<dim3(T_ / 2, G4 / 128), 256, 0, s2>>>(values);
    cudaEventRecord(ev2, s2);

    k_scan<<<NB_SCAN, 256, smem>>>(W_hh, Deltas, out);

    // join
    cudaStreamWaitEvent(0, ev2, 0);
}